// round 8
// baseline (speedup 1.0000x reference)
#include <cuda_runtime.h>
#include <cstdint>

#define T_SEQ 2048
#define BATCH 256
#define HID   64
#define INP   7
#define XSTEPS 64                    // steps per prefetch block
#define XBLK_FLOATS (XSTEPS * INP)   // 448 floats per block in GMEM

typedef unsigned long long ull;

__device__ __forceinline__ ull fma2(ull a, ull b, ull c) {
    ull d;
    asm("fma.rn.f32x2 %0, %1, %2, %3;" : "=l"(d) : "l"(a), "l"(b), "l"(c));
    return d;
}
__device__ __forceinline__ ull add2(ull a, ull b) {
    ull d;
    asm("add.rn.f32x2 %0, %1, %2;" : "=l"(d) : "l"(a), "l"(b));
    return d;
}
__device__ __forceinline__ ull pack2(float lo, float hi) {
    ull d; asm("mov.b64 %0, {%1, %2};" : "=l"(d) : "f"(lo), "f"(hi)); return d;
}
__device__ __forceinline__ float2 unpack2(ull a) {
    float2 r; asm("mov.b64 {%0, %1}, %2;" : "=f"(r.x), "=f"(r.y) : "l"(a)); return r;
}
__device__ __forceinline__ float htanh(float x) {
    float y; asm("tanh.approx.f32 %0, %1;" : "=f"(y) : "f"(x)); return y;
}
__device__ __forceinline__ void cpa4(uint32_t dst_smem, const float* src) {
    asm volatile("cp.async.ca.shared.global [%0], [%1], 4;" :: "r"(dst_smem), "l"(src));
}
__device__ __forceinline__ void cp_commit() {
    asm volatile("cp.async.commit_group;" ::: "memory");
}
__device__ __forceinline__ void cp_wait0() {
    asm volatile("cp.async.wait_group 0;" ::: "memory");
}

// grid = 128 CTAs x 512 threads; CTA runs 2 independent batch chains
// (chain = tid>>8), each chain = 256 threads = 8 warps, per-chain named bars,
// chains staggered ~half a step (one-time delay chain on chain 1).
//
// K-SPLIT layout: thread w in [0,256): q = w&1 (h-half), p = (w>>1)&1 (gate
// pair), u = w>>2 (hidden unit). Thread computes rows rA = p*64+u (i/f) and
// rB = rA+128 (g/o) over h[32q : 32q+32] only:
//   - weights: 2 rows x 16 ull = 64 regs (fits 128-reg cap at 512 thr)
//   - per-step: 8 LDS.128 (h half) + 32 FMA2, HALF the chain length of the
//     2-warp/SMSP layout, with 4 warps/SMSP to hide latency.
// K-halves combined with shfl_xor(1); gate exchange with shfl_xor(2); all 4
// lanes of a unit-nibble redundantly update c (uniform, no divergence);
// lane (w&3)==0 stores h. ONE named barrier per step; h double-buffered.
// xz (x·Wih + bias, h-independent) is computed in the tail shadow for t+1
// via a running pointer into the cp.async x ring (1 LDS.128 + 4 FMA2).
//
// Backward direction = ONE LSTM step on x[T-1] from zero state, fused with
// the final linear as an epilogue.
struct ChainSmem {
    float h[2][64];             // double-buffered hidden state
    float hb[64];               // backward h (epilogue)
    float xring[2][XSTEPS * 8]; // padded x ring, 2 blocks
};

__global__ void __launch_bounds__(512, 1)
bilstm_kernel(const float* __restrict__ x,      // [B,T,I]
              const float* __restrict__ Wih_f,  // [256,7]
              const float* __restrict__ Whh_f,  // [256,64]
              const float* __restrict__ bih_f,  // [256]
              const float* __restrict__ bhh_f,  // [256]
              const float* __restrict__ Wih_b,  // [256,7]
              const float* __restrict__ Whh_b,  // unused (h0 = 0 for single bwd step)
              const float* __restrict__ bih_b,  // [256]
              const float* __restrict__ bhh_b,  // [256]
              const float* __restrict__ Wlin,   // [3,128]
              const float* __restrict__ blin,   // [3]
              float* __restrict__ out)          // [B,3]
{
    __shared__ __align__(16) ChainSmem cs[2];

    const int tid   = threadIdx.x;
    const int chain = tid >> 8;          // 0 or 1
    const int w     = tid & 255;         // within-chain thread id
    const int q     = w & 1;             // h-half selector
    const int p     = (w >> 1) & 1;      // gate pair selector
    const int u     = w >> 2;            // hidden unit
    const int rA    = p * 64 + u;        // gate i (p=0) / f (p=1)
    const int rB    = rA + 128;          // gate g (p=0) / o (p=1)
    const int b     = blockIdx.x * 2 + chain;
    const int barid = 1 + chain;
    ChainSmem& S = cs[chain];

    const float* xb = x + (size_t)b * T_SEQ * INP;

    const uint32_t ring0 = (uint32_t)__cvta_generic_to_shared(&S.xring[0][0]);
    const uint32_t ring1 = (uint32_t)__cvta_generic_to_shared(&S.xring[1][0]);

    // ring fill: each of 256 threads copies 2 padded elements per block
    const int e0 = 2 * w, e1 = 2 * w + 1;
    const int s0 = e0 >> 3, j0 = e0 & 7;
    const int s1 = e1 >> 3, j1 = e1 & 7;

    // activation of row B: tanh for p=0 (gate g), sigmoid for p=1 (gate o)
    const float actB_s = (p == 0) ? 1.0f : 0.5f;
    const float actB_m = (p == 0) ? 1.0f : 0.5f;
    const float actB_b = (p == 0) ? 0.0f : 0.5f;

    // ---- weights into registers: 2 rows x half-K = 2 x 16 ull ----
    ull wA[16], wB[16];
    {
        const ull* a  = reinterpret_cast<const ull*>(Whh_f + rA * HID + q * 32);
        const ull* c2 = reinterpret_cast<const ull*>(Whh_f + rB * HID + q * 32);
#pragma unroll
        for (int m = 0; m < 16; m++) wA[m] = a[m];
#pragma unroll
        for (int m = 0; m < 16; m++) wB[m] = c2[m];
    }
    // Wih halves: q=0 -> x[0..3], q=1 -> x[4..7] (x[7] is zero pad)
    ull wihA0, wihA1, wihB0, wihB1;
    {
        float t4[4];
#pragma unroll
        for (int k = 0; k < 4; k++) {
            int idx = 4 * q + k;
            t4[k] = (idx < INP) ? Wih_f[rA * INP + idx] : 0.0f;
        }
        wihA0 = pack2(t4[0], t4[1]); wihA1 = pack2(t4[2], t4[3]);
#pragma unroll
        for (int k = 0; k < 4; k++) {
            int idx = 4 * q + k;
            t4[k] = (idx < INP) ? Wih_b[0] * 0.0f + Wih_f[rB * INP + idx] : 0.0f;
        }
        wihB0 = pack2(t4[0], t4[1]); wihB1 = pack2(t4[2], t4[3]);
    }
    // bias folded into xz on the q==0 lane only (avoid double count)
    const ull biasA2 = (q == 0) ? pack2(bih_f[rA] + bhh_f[rA], 0.0f) : 0ull;
    const ull biasB2 = (q == 0) ? pack2(bih_f[rB] + bhh_f[rB], 0.0f) : 0ull;

    // ---- init: h=0, zero ring pad slots, prefetch blocks 0 and 1 ----
    if (w < 64) S.h[0][w] = 0.0f;
    if (w < 128) {
        int bufi = w >> 6, s = w & 63;
        S.xring[bufi][s * 8 + 7] = 0.0f;
    }
    if (j0 < INP) cpa4(ring0 + (uint32_t)e0 * 4, xb + s0 * INP + j0);
    if (j1 < INP) cpa4(ring0 + (uint32_t)e1 * 4, xb + s1 * INP + j1);
    cp_commit();
    if (j0 < INP) cpa4(ring1 + (uint32_t)e0 * 4, xb + XBLK_FLOATS + s0 * INP + j0);
    if (j1 < INP) cpa4(ring1 + (uint32_t)e1 * 4, xb + XBLK_FLOATS + s1 * INP + j1);
    cp_commit();
    cp_wait0();
    float c = 0.0f;
    __syncthreads();

    // ---- one-time stagger: chain 1 burns ~half a step so the two chains
    // run anti-phase; per-step times are identical so the offset persists ----
    if (chain == 1) {
        float d = actB_b + 1.5f;
#pragma unroll
        for (int i = 0; i < 50; i++) d = fmaf(d, 0.9999999f, 1e-9f);
        asm volatile("" :: "f"(d));
    }

    // xz for t=0; xnext = ring position for the NEXT xz computation
    ull xzA0, xzA1, xzB0, xzB1;
    const float* xnext;
    {
        const ulonglong2* xv2 = reinterpret_cast<const ulonglong2*>(&S.xring[0][4 * q]);
        ulonglong2 xv = *xv2;
        xzA0 = fma2(wihA0, xv.x, biasA2);
        xzA1 = fma2(wihA1, xv.y, 0ull);
        xzB0 = fma2(wihB0, xv.x, biasB2);
        xzB1 = fma2(wihB1, xv.y, 0ull);
        xnext = &S.xring[0][8 + 4 * q];
    }

    for (int t = 0; t < T_SEQ; t++) {
        if ((t & (XSTEPS - 1)) == 0 && t) {
            cp_wait0();   // block issued 64 steps ago has landed
            asm volatile("bar.sync %0, 256;" :: "r"(barid) : "memory");
            int nb = (t >> 6) + 1;
            if (nb < T_SEQ / XSTEPS) {
                uint32_t dst = (nb & 1) ? ring1 : ring0;
                const float* src = xb + (size_t)nb * XBLK_FLOATS;
                if (j0 < INP) cpa4(dst + (uint32_t)e0 * 4, src + s0 * INP + j0);
                if (j1 < INP) cpa4(dst + (uint32_t)e1 * 4, src + s1 * INP + j1);
            }
            cp_commit();
            // xz for THIS boundary step from the just-waited buffer
            const float* xcur = &S.xring[(t >> 6) & 1][4 * q];
            ulonglong2 xv = *reinterpret_cast<const ulonglong2*>(xcur);
            xzA0 = fma2(wihA0, xv.x, biasA2);
            xzA1 = fma2(wihA1, xv.y, 0ull);
            xzB0 = fma2(wihB0, xv.x, biasB2);
            xzB1 = fma2(wihB1, xv.y, 0ull);
            xnext = xcur + 8;
        }

        // z-half = xz + W_hh[:, qhalf]·h[qhalf]
        ull a0 = xzA0, a1 = xzA1;
        ull b0 = xzB0, b1 = xzB1;
        const ulonglong2* h2 = reinterpret_cast<const ulonglong2*>(
            S.h[t & 1] + (q << 5));
#pragma unroll
        for (int m = 0; m < 4; m++) {
            ulonglong2 ha  = h2[2 * m];
            ulonglong2 hbv = h2[2 * m + 1];
            a0 = fma2(wA[4 * m + 0], ha.x,  a0);
            a1 = fma2(wA[4 * m + 1], ha.y,  a1);
            b0 = fma2(wB[4 * m + 0], ha.x,  b0);
            b1 = fma2(wB[4 * m + 1], ha.y,  b1);
            a0 = fma2(wA[4 * m + 2], hbv.x, a0);
            a1 = fma2(wA[4 * m + 3], hbv.y, a1);
            b0 = fma2(wB[4 * m + 2], hbv.x, b0);
            b1 = fma2(wB[4 * m + 3], hbv.y, b1);
        }
        float2 fa = unpack2(add2(a0, a1));
        float2 fb = unpack2(add2(b0, b1));
        float zA = fa.x + fa.y;
        float zB = fb.x + fb.y;
        // combine K-halves (lane-pair over q)
        zA += __shfl_xor_sync(0xFFFFFFFFu, zA, 1);
        zB += __shfl_xor_sync(0xFFFFFFFFu, zB, 1);

        // activations: row A sigmoid (i or f); row B tanh (g) / sigmoid (o)
        float aA = fmaf(0.5f, htanh(0.5f * zA), 0.5f);
        float aB = fmaf(actB_m, htanh(actB_s * zB), actB_b);

        // gate exchange across p (lane distance 2)
        float rAv = __shfl_xor_sync(0xFFFFFFFFu, aA, 2);
        float rBv = __shfl_xor_sync(0xFFFFFFFFu, aB, 2);
        float gi_ = (p == 0) ? aA  : rAv;   // i
        float gf_ = (p == 0) ? rAv : aA;    // f
        float gg_ = (p == 0) ? aB  : rBv;   // g
        float go_ = (p == 0) ? rBv : aB;    // o
        c = gf_ * c + gi_ * gg_;            // redundant on all 4 nibble lanes
        float hn = go_ * htanh(c);
        if ((w & 3) == 0) S.h[(t & 1) ^ 1][u] = hn;

        // tail shadow: xz for t+1 (non-boundary successors)
        if (((t + 1) & (XSTEPS - 1)) != 0 && t + 1 < T_SEQ) {
            ulonglong2 xv = *reinterpret_cast<const ulonglong2*>(xnext);
            xzA0 = fma2(wihA0, xv.x, biasA2);
            xzA1 = fma2(wihA1, xv.y, 0ull);
            xzB0 = fma2(wihB0, xv.x, biasB2);
            xzB1 = fma2(wihB1, xv.y, 0ull);
            xnext += 8;
        }
        asm volatile("bar.sync %0, 256;" :: "r"(barid) : "memory");
    }

    // ---- backward direction: ONE step on x[T-1] from zero state ----
    {
        const float* xl = &S.xring[1][63 * 8];   // t=2047 -> buf 1, slot 63
        float zbA = bih_b[rA] + bhh_b[rA];
        float zbB = bih_b[rB] + bhh_b[rB];
#pragma unroll
        for (int i = 0; i < INP; i++) {
            zbA += Wih_b[rA * INP + i] * xl[i];
            zbB += Wih_b[rB * INP + i] * xl[i];
        }
        float aA = fmaf(0.5f, htanh(0.5f * zbA), 0.5f);
        float aB = fmaf(actB_m, htanh(actB_s * zbB), actB_b);
        float rAv = __shfl_xor_sync(0xFFFFFFFFu, aA, 2);
        float rBv = __shfl_xor_sync(0xFFFFFFFFu, aB, 2);
        float gi_ = (p == 0) ? aA  : rAv;
        float gg_ = (p == 0) ? aB  : rBv;
        float go_ = (p == 0) ? rBv : aB;
        float cb = gi_ * gg_;                // f*c0 == 0
        if ((w & 3) == 0) S.hb[u] = go_ * htanh(cb);
        asm volatile("bar.sync %0, 256;" :: "r"(barid) : "memory");
    }

    // ---- final linear: out[b] = W_lin @ concat(h_f, h_b) + b_lin ----
    // final forward h is in S.h[0] (t=2047 writes buffer (2047&1)^1 = 0)
    if (w < 3) {
        float a = blin[w];
#pragma unroll 16
        for (int k = 0; k < 64; k++) a += Wlin[w * 128 + k] * S.h[0][k];
#pragma unroll 16
        for (int k = 0; k < 64; k++) a += Wlin[w * 128 + 64 + k] * S.hb[k];
        out[b * 3 + w] = a;
    }
}

extern "C" void kernel_launch(void* const* d_in, const int* in_sizes, int n_in,
                              void* d_out, int out_size) {
    (void)in_sizes; (void)n_in; (void)out_size;
    bilstm_kernel<<<BATCH / 2, 512>>>(
        (const float*)d_in[0],  (const float*)d_in[1], (const float*)d_in[2],
        (const float*)d_in[3],  (const float*)d_in[4], (const float*)d_in[5],
        (const float*)d_in[6],  (const float*)d_in[7], (const float*)d_in[8],
        (const float*)d_in[9],  (const float*)d_in[10], (float*)d_out);
}

// round 9
// speedup vs baseline: 1.1266x; 1.1266x over previous
#include <cuda_runtime.h>
#include <cstdint>

#define T_SEQ 2048
#define BATCH 256
#define HID   64
#define INP   7
#define XSTEPS 64                    // steps per prefetch block
#define XBLK_FLOATS (XSTEPS * INP)   // 448 floats per block in GMEM

typedef unsigned long long ull;

__device__ __forceinline__ ull fma2(ull a, ull b, ull c) {
    ull d;
    asm("fma.rn.f32x2 %0, %1, %2, %3;" : "=l"(d) : "l"(a), "l"(b), "l"(c));
    return d;
}
__device__ __forceinline__ ull add2(ull a, ull b) {
    ull d;
    asm("add.rn.f32x2 %0, %1, %2;" : "=l"(d) : "l"(a), "l"(b));
    return d;
}
__device__ __forceinline__ ull pack2(float lo, float hi) {
    ull d; asm("mov.b64 %0, {%1, %2};" : "=l"(d) : "f"(lo), "f"(hi)); return d;
}
__device__ __forceinline__ float2 unpack2(ull a) {
    float2 r; asm("mov.b64 {%0, %1}, %2;" : "=f"(r.x), "=f"(r.y) : "l"(a)); return r;
}
__device__ __forceinline__ float htanh(float x) {
    float y; asm("tanh.approx.f32 %0, %1;" : "=f"(y) : "f"(x)); return y;
}
__device__ __forceinline__ void cpa4(uint32_t dst_smem, const float* src) {
    asm volatile("cp.async.ca.shared.global [%0], [%1], 4;" :: "r"(dst_smem), "l"(src));
}
__device__ __forceinline__ void cp_commit() {
    asm volatile("cp.async.commit_group;" ::: "memory");
}
__device__ __forceinline__ void cp_wait0() {
    asm volatile("cp.async.wait_group 0;" ::: "memory");
}

// grid = 128 CTAs x 128 threads; ONE CTA processes TWO batch chains in a
// single instruction stream. Model weights are identical across batch, so
// each thread's register-resident weights (2 gate rows x 32 f32x2) feed
// 2 x 64 FMA2 on 8 independent accumulators (4 per batch). The serial tail
// (z-reduce, MUFU.TANH, shfl gate exchange, c/h update) is two independent
// ILP-2 chains the scheduler interleaves, so its latency is paid once, not
// twice. One warp per SMSP saturates the FMA pipe (rt=2); one plain
// __syncthreads() per step across 4 warps.
//
// Thread w in [0,128): p = w&1 (gate pair), u = w>>1 (hidden unit),
//   rowA = p*64+u (i/f), rowB = rowA+128 (g/o).
// Gate exchange = shfl_xor(1); p==0 lanes update c and write h
// (double-buffered per batch). x streamed via cp.async double-buffered
// 64-step rings (8-float padded rows), one ring per batch; xz (x·Wih + bias)
// precomputed in the tail shadow for t+1.
//
// Backward direction = ONE LSTM step on x[T-1] from zero state (scan[0] of
// the reversed sequence), fused as an epilogue with the final linear.
struct Smem {
    float h[2][2][64];             // [batch][buf][unit]
    float hb[2][64];               // backward h per batch (epilogue)
    float xring[2][2][XSTEPS * 8]; // [batch][buf][slot*8 padded]
};

__global__ void __launch_bounds__(128, 1)
bilstm_kernel(const float* __restrict__ x,      // [B,T,I]
              const float* __restrict__ Wih_f,  // [256,7]
              const float* __restrict__ Whh_f,  // [256,64]
              const float* __restrict__ bih_f,  // [256]
              const float* __restrict__ bhh_f,  // [256]
              const float* __restrict__ Wih_b,  // [256,7]
              const float* __restrict__ Whh_b,  // unused (h0 = 0 for single bwd step)
              const float* __restrict__ bih_b,  // [256]
              const float* __restrict__ bhh_b,  // [256]
              const float* __restrict__ Wlin,   // [3,128]
              const float* __restrict__ blin,   // [3]
              float* __restrict__ out)          // [B,3]
{
    __shared__ __align__(16) Smem S;

    const int w  = threadIdx.x;
    const int p  = w & 1;            // gate pair selector
    const int u  = w >> 1;           // hidden unit
    const int rA = p * 64 + u;       // gate i (p=0) / f (p=1)
    const int rB = rA + 128;         // gate g (p=0) / o (p=1)
    const int b0 = blockIdx.x * 2;

    const float* xb0 = x + (size_t)b0 * T_SEQ * INP;
    const float* xb1 = x + (size_t)(b0 + 1) * T_SEQ * INP;

    // ring-fill role: thread fills slot (w&63) of batch (w>>6)
    const int tb   = w >> 6;
    const int slot = w & 63;
    const float* xbt = tb ? xb1 : xb0;
    const uint32_t ringt0 = (uint32_t)__cvta_generic_to_shared(&S.xring[tb][0][0]);
    const uint32_t ringt1 = (uint32_t)__cvta_generic_to_shared(&S.xring[tb][1][0]);

    // activation of row B: tanh for p=0 (gate g), sigmoid for p=1 (gate o)
    const float actB_s = (p == 0) ? 1.0f : 0.5f;
    const float actB_m = (p == 0) ? 1.0f : 0.5f;
    const float actB_b = (p == 0) ? 0.0f : 0.5f;

    // ---- weights into registers: 2 rows x 32 f32x2 (shared across batches) ----
    ull wA[32], wB[32];
    {
        const ull* a  = reinterpret_cast<const ull*>(Whh_f + rA * HID);
        const ull* c2 = reinterpret_cast<const ull*>(Whh_f + rB * HID);
#pragma unroll
        for (int m = 0; m < 32; m++) wA[m] = a[m];
#pragma unroll
        for (int m = 0; m < 32; m++) wB[m] = c2[m];
    }
    ull wihA[4], wihB[4];
    {
        float t[8];
#pragma unroll
        for (int i = 0; i < INP; i++) t[i] = Wih_f[rA * INP + i];
        t[7] = 0.0f;
#pragma unroll
        for (int m = 0; m < 4; m++) wihA[m] = pack2(t[2 * m], t[2 * m + 1]);
#pragma unroll
        for (int i = 0; i < INP; i++) t[i] = Wih_f[rB * INP + i];
        t[7] = 0.0f;
#pragma unroll
        for (int m = 0; m < 4; m++) wihB[m] = pack2(t[2 * m], t[2 * m + 1]);
    }
    const ull biasA2 = pack2(bih_f[rA] + bhh_f[rA], 0.0f);
    const ull biasB2 = pack2(bih_f[rB] + bhh_f[rB], 0.0f);

    // ---- init: h=0 (both batches), zero ring pads, prefetch blocks 0,1 ----
    if (w < 64) { S.h[0][0][w] = 0.0f; S.h[1][0][w] = 0.0f; }
    S.xring[tb][0][slot * 8 + 7] = 0.0f;
    S.xring[tb][1][slot * 8 + 7] = 0.0f;
#pragma unroll
    for (int k = 0; k < 7; k++)
        cpa4(ringt0 + (uint32_t)(slot * 8 + k) * 4, xbt + slot * INP + k);
    cp_commit();
#pragma unroll
    for (int k = 0; k < 7; k++)
        cpa4(ringt1 + (uint32_t)(slot * 8 + k) * 4, xbt + XBLK_FLOATS + slot * INP + k);
    cp_commit();
    cp_wait0();
    float c0 = 0.0f, c1 = 0.0f;
    __syncthreads();

    // xz accumulators per batch (h-independent part + bias) for t=0
    ull xA0_0, xA1_0, xB0_0, xB1_0;   // batch0
    ull xA0_1, xA1_1, xB0_1, xB1_1;   // batch1
    const float* xnext0;
    const float* xnext1;
    {
        ulonglong2 xv = *reinterpret_cast<const ulonglong2*>(&S.xring[0][0][0]);
        ulonglong2 xw = *reinterpret_cast<const ulonglong2*>(&S.xring[0][0][4]);
        xA0_0 = fma2(wihA[0], xv.x, biasA2);
        xA1_0 = fma2(wihA[1], xv.y, 0ull);
        xB0_0 = fma2(wihB[0], xv.x, biasB2);
        xB1_0 = fma2(wihB[1], xv.y, 0ull);
        xA0_0 = fma2(wihA[2], xw.x, xA0_0);
        xA1_0 = fma2(wihA[3], xw.y, xA1_0);
        xB0_0 = fma2(wihB[2], xw.x, xB0_0);
        xB1_0 = fma2(wihB[3], xw.y, xB1_0);
        ulonglong2 yv = *reinterpret_cast<const ulonglong2*>(&S.xring[1][0][0]);
        ulonglong2 yw = *reinterpret_cast<const ulonglong2*>(&S.xring[1][0][4]);
        xA0_1 = fma2(wihA[0], yv.x, biasA2);
        xA1_1 = fma2(wihA[1], yv.y, 0ull);
        xB0_1 = fma2(wihB[0], yv.x, biasB2);
        xB1_1 = fma2(wihB[1], yv.y, 0ull);
        xA0_1 = fma2(wihA[2], yw.x, xA0_1);
        xA1_1 = fma2(wihA[3], yw.y, xA1_1);
        xB0_1 = fma2(wihB[2], yw.x, xB0_1);
        xB1_1 = fma2(wihB[3], yw.y, xB1_1);
        xnext0 = &S.xring[0][0][8];
        xnext1 = &S.xring[1][0][8];
    }

    for (int t = 0; t < T_SEQ; t++) {
        if ((t & (XSTEPS - 1)) == 0 && t) {
            cp_wait0();   // block issued 64 steps ago has landed
            __syncthreads();
            int nb = (t >> 6) + 1;
            if (nb < T_SEQ / XSTEPS) {
                uint32_t dst = (nb & 1) ? ringt1 : ringt0;
                const float* src = xbt + (size_t)nb * XBLK_FLOATS + slot * INP;
#pragma unroll
                for (int k = 0; k < 7; k++)
                    cpa4(dst + (uint32_t)(slot * 8 + k) * 4, src + k);
            }
            cp_commit();
            // xz for THIS boundary step, both batches
            const float* xc0 = &S.xring[0][(t >> 6) & 1][0];
            const float* xc1 = &S.xring[1][(t >> 6) & 1][0];
            ulonglong2 xv = *reinterpret_cast<const ulonglong2*>(xc0);
            ulonglong2 xw = *reinterpret_cast<const ulonglong2*>(xc0 + 4);
            xA0_0 = fma2(wihA[0], xv.x, biasA2);
            xA1_0 = fma2(wihA[1], xv.y, 0ull);
            xB0_0 = fma2(wihB[0], xv.x, biasB2);
            xB1_0 = fma2(wihB[1], xv.y, 0ull);
            xA0_0 = fma2(wihA[2], xw.x, xA0_0);
            xA1_0 = fma2(wihA[3], xw.y, xA1_0);
            xB0_0 = fma2(wihB[2], xw.x, xB0_0);
            xB1_0 = fma2(wihB[3], xw.y, xB1_0);
            ulonglong2 yv = *reinterpret_cast<const ulonglong2*>(xc1);
            ulonglong2 yw = *reinterpret_cast<const ulonglong2*>(xc1 + 4);
            xA0_1 = fma2(wihA[0], yv.x, biasA2);
            xA1_1 = fma2(wihA[1], yv.y, 0ull);
            xB0_1 = fma2(wihB[0], yv.x, biasB2);
            xB1_1 = fma2(wihB[1], yv.y, 0ull);
            xA0_1 = fma2(wihA[2], yw.x, xA0_1);
            xA1_1 = fma2(wihA[3], yw.y, xA1_1);
            xB0_1 = fma2(wihB[2], yw.x, xB0_1);
            xB1_1 = fma2(wihB[3], yw.y, xB1_1);
            xnext0 = xc0 + 8;
            xnext1 = xc1 + 8;
        }

        // z = xz + W_hh·h for both batches (8 independent accumulators)
        ull a0 = xA0_0, a1 = xA1_0, b0a = xB0_0, b1a = xB1_0;
        ull c0a = xA0_1, c1a = xA1_1, d0a = xB0_1, d1a = xB1_1;
        const ulonglong2* h0q = reinterpret_cast<const ulonglong2*>(S.h[0][t & 1]);
        const ulonglong2* h1q = reinterpret_cast<const ulonglong2*>(S.h[1][t & 1]);
#pragma unroll
        for (int m = 0; m < 8; m++) {
            ulonglong2 ha = h0q[2 * m];
            ulonglong2 hb = h0q[2 * m + 1];
            a0  = fma2(wA[4 * m + 0], ha.x, a0);
            a1  = fma2(wA[4 * m + 1], ha.y, a1);
            b0a = fma2(wB[4 * m + 0], ha.x, b0a);
            b1a = fma2(wB[4 * m + 1], ha.y, b1a);
            a0  = fma2(wA[4 * m + 2], hb.x, a0);
            a1  = fma2(wA[4 * m + 3], hb.y, a1);
            b0a = fma2(wB[4 * m + 2], hb.x, b0a);
            b1a = fma2(wB[4 * m + 3], hb.y, b1a);
            ulonglong2 ga = h1q[2 * m];
            ulonglong2 gb = h1q[2 * m + 1];
            c0a = fma2(wA[4 * m + 0], ga.x, c0a);
            c1a = fma2(wA[4 * m + 1], ga.y, c1a);
            d0a = fma2(wB[4 * m + 0], ga.x, d0a);
            d1a = fma2(wB[4 * m + 1], ga.y, d1a);
            c0a = fma2(wA[4 * m + 2], gb.x, c0a);
            c1a = fma2(wA[4 * m + 3], gb.y, c1a);
            d0a = fma2(wB[4 * m + 2], gb.x, d0a);
            d1a = fma2(wB[4 * m + 3], gb.y, d1a);
        }
        float2 fA0 = unpack2(add2(a0, a1));
        float2 fB0 = unpack2(add2(b0a, b1a));
        float2 fA1 = unpack2(add2(c0a, c1a));
        float2 fB1 = unpack2(add2(d0a, d1a));
        float zA0 = fA0.x + fA0.y;
        float zB0 = fB0.x + fB0.y;
        float zA1 = fA1.x + fA1.y;
        float zB1 = fB1.x + fB1.y;

        // activations (row A sigmoid; row B tanh(g)/sigmoid(o)), 2 batches in ILP
        float aA0 = fmaf(0.5f, htanh(0.5f * zA0), 0.5f);
        float aB0 = fmaf(actB_m, htanh(actB_s * zB0), actB_b);
        float aA1 = fmaf(0.5f, htanh(0.5f * zA1), 0.5f);
        float aB1 = fmaf(actB_m, htanh(actB_s * zB1), actB_b);

        // exchange within lane pair: p=0 holds (i,g); gets (f,o) from p=1
        float oA0 = __shfl_xor_sync(0xFFFFFFFFu, aA0, 1);
        float oB0 = __shfl_xor_sync(0xFFFFFFFFu, aB0, 1);
        float oA1 = __shfl_xor_sync(0xFFFFFFFFu, aA1, 1);
        float oB1 = __shfl_xor_sync(0xFFFFFFFFu, aB1, 1);
        if (p == 0) {
            c0 = oA0 * c0 + aA0 * aB0;
            S.h[0][(t & 1) ^ 1][u] = oB0 * htanh(c0);
            c1 = oA1 * c1 + aA1 * aB1;
            S.h[1][(t & 1) ^ 1][u] = oB1 * htanh(c1);
        }

        // tail shadow: xz for t+1 (non-boundary successors)
        if (((t + 1) & (XSTEPS - 1)) != 0 && t + 1 < T_SEQ) {
            ulonglong2 xv = *reinterpret_cast<const ulonglong2*>(xnext0);
            ulonglong2 xw = *reinterpret_cast<const ulonglong2*>(xnext0 + 4);
            xA0_0 = fma2(wihA[0], xv.x, biasA2);
            xA1_0 = fma2(wihA[1], xv.y, 0ull);
            xB0_0 = fma2(wihB[0], xv.x, biasB2);
            xB1_0 = fma2(wihB[1], xv.y, 0ull);
            xA0_0 = fma2(wihA[2], xw.x, xA0_0);
            xA1_0 = fma2(wihA[3], xw.y, xA1_0);
            xB0_0 = fma2(wihB[2], xw.x, xB0_0);
            xB1_0 = fma2(wihB[3], xw.y, xB1_0);
            ulonglong2 yv = *reinterpret_cast<const ulonglong2*>(xnext1);
            ulonglong2 yw = *reinterpret_cast<const ulonglong2*>(xnext1 + 4);
            xA0_1 = fma2(wihA[0], yv.x, biasA2);
            xA1_1 = fma2(wihA[1], yv.y, 0ull);
            xB0_1 = fma2(wihB[0], yv.x, biasB2);
            xB1_1 = fma2(wihB[1], yv.y, 0ull);
            xA0_1 = fma2(wihA[2], yw.x, xA0_1);
            xA1_1 = fma2(wihA[3], yw.y, xA1_1);
            xB0_1 = fma2(wihB[2], yw.x, xB0_1);
            xB1_1 = fma2(wihB[3], yw.y, xB1_1);
            xnext0 += 8;
            xnext1 += 8;
        }
        __syncthreads();
    }

    // ---- backward direction: ONE step on x[T-1] from zero state ----
    {
        const float* xl0 = &S.xring[0][1][63 * 8];   // t=2047 -> buf 1, slot 63
        const float* xl1 = &S.xring[1][1][63 * 8];
        float zbA0 = bih_b[rA] + bhh_b[rA];
        float zbB0 = bih_b[rB] + bhh_b[rB];
        float zbA1 = zbA0, zbB1 = zbB0;
#pragma unroll
        for (int i = 0; i < INP; i++) {
            float wa = Wih_b[rA * INP + i], wb = Wih_b[rB * INP + i];
            zbA0 += wa * xl0[i];
            zbB0 += wb * xl0[i];
            zbA1 += wa * xl1[i];
            zbB1 += wb * xl1[i];
        }
        float aA0 = fmaf(0.5f, htanh(0.5f * zbA0), 0.5f);
        float aB0 = fmaf(actB_m, htanh(actB_s * zbB0), actB_b);
        float aA1 = fmaf(0.5f, htanh(0.5f * zbA1), 0.5f);
        float aB1 = fmaf(actB_m, htanh(actB_s * zbB1), actB_b);
        float oB0 = __shfl_xor_sync(0xFFFFFFFFu, aB0, 1);
        float oB1 = __shfl_xor_sync(0xFFFFFFFFu, aB1, 1);
        if (p == 0) {
            S.hb[0][u] = oB0 * htanh(aA0 * aB0);   // f*c0 == 0
            S.hb[1][u] = oB1 * htanh(aA1 * aB1);
        }
        __syncthreads();
    }

    // ---- final linear: out[b] = W_lin @ concat(h_f, h_b) + b_lin ----
    // final forward h is in S.h[batch][0] (t=2047 writes buffer 0)
    if ((w & 63) < 3) {
        int batch = w >> 6;
        int o = w & 63;
        float a = blin[o];
#pragma unroll 16
        for (int k = 0; k < 64; k++) a += Wlin[o * 128 + k] * S.h[batch][0][k];
#pragma unroll 16
        for (int k = 0; k < 64; k++) a += Wlin[o * 128 + 64 + k] * S.hb[batch][k];
        out[(b0 + batch) * 3 + o] = a;
    }
}

extern "C" void kernel_launch(void* const* d_in, const int* in_sizes, int n_in,
                              void* d_out, int out_size) {
    (void)in_sizes; (void)n_in; (void)out_size;
    bilstm_kernel<<<BATCH / 2, 128>>>(
        (const float*)d_in[0],  (const float*)d_in[1], (const float*)d_in[2],
        (const float*)d_in[3],  (const float*)d_in[4], (const float*)d_in[5],
        (const float*)d_in[6],  (const float*)d_in[7], (const float*)d_in[8],
        (const float*)d_in[9],  (const float*)d_in[10], (float*)d_out);
}